// round 2
// baseline (speedup 1.0000x reference)
#include <cuda_runtime.h>
#include <cuda_fp16.h>
#include <cstdint>

#define TS    512
#define NBAT  512
#define HID   128
#define INP   32
#define G4    512
#define NB    8
#define HSTR  136   // padded h_sm row stride (halfs) -> conflict-free B-frag reads
#define XSTR  40    // padded x_sm row stride (halfs)

// ---------------- device-global scratch (no runtime allocation allowed) ----------------
__device__ __half g_WencHH[G4 * HID];          // enc_Whh fp16
__device__ __half g_WencIH[G4 * INP];          // enc_Wih fp16
__device__ __half g_Wcomb [G4 * HID];          // dec_Wih + dec_Whh fp16
__device__ float  g_benc[G4];                  // enc_bih + enc_bhh
__device__ float  g_bdec[G4];                  // dec_bih + dec_bhh
__device__ __half g_fcW[INP * HID];            // fc_W fp16
__device__ __half g_xT[(size_t)TS * NBAT * INP];         // [t][b][i]  16MB
__device__ __half g_ench[NBAT * HID];          // encoder final h (fp16)
__device__ float  g_encc[NBAT * HID];          // encoder final c (fp32)
__device__ __half g_dech[(size_t)TS * NBAT * HID];       // [t][b][h]  64MB

// ---------------- fast accurate activations (ex2+rcp: ~1e-7 abs err) ----------------
__device__ __forceinline__ float fast_ex2(float x) {
    float r; asm("ex2.approx.f32 %0, %1;" : "=f"(r) : "f"(x)); return r;
}
__device__ __forceinline__ float fast_rcp(float x) {
    float r; asm("rcp.approx.f32 %0, %1;" : "=f"(r) : "f"(x)); return r;
}
__device__ __forceinline__ float sigf(float x) {
    // 1/(1+2^(-x*log2e))
    return fast_rcp(1.0f + fast_ex2(-1.4426950408889634f * x));
}
__device__ __forceinline__ float tanhf_fast(float x) {
    // 1 - 2/(2^(2x*log2e)+1)   (correct limits at +/-inf)
    float e = fast_ex2(2.8853900817779268f * x);
    return fmaf(-2.0f, fast_rcp(e + 1.0f), 1.0f);
}

// ---------------- mma.m16n8k16 row.col f32.f16.f16.f32 ----------------
#define MMA16816(acc, a, b)                                                        \
    asm("mma.sync.aligned.m16n8k16.row.col.f32.f16.f16.f32 "                       \
        "{%0,%1,%2,%3}, {%4,%5,%6,%7}, {%8,%9}, {%0,%1,%2,%3};"                    \
        : "+f"(acc[0]), "+f"(acc[1]), "+f"(acc[2]), "+f"(acc[3])                   \
        : "r"(a[0]), "r"(a[1]), "r"(a[2]), "r"(a[3]), "r"(b[0]), "r"(b[1]))

// ======================= prep: weight conversion =======================
__global__ void prep_weights(const float* __restrict__ eWih, const float* __restrict__ eWhh,
                             const float* __restrict__ ebih, const float* __restrict__ ebhh,
                             const float* __restrict__ dWih, const float* __restrict__ dWhh,
                             const float* __restrict__ dbih, const float* __restrict__ dbhh,
                             const float* __restrict__ fcW) {
    int n = blockIdx.x * blockDim.x + threadIdx.x;
    if (n < G4 * HID) {
        g_WencHH[n] = __float2half(eWhh[n]);
        g_Wcomb[n]  = __float2half(dWih[n] + dWhh[n]);
    }
    if (n < G4 * INP) g_WencIH[n] = __float2half(eWih[n]);
    if (n < INP * HID) g_fcW[n] = __float2half(fcW[n]);
    if (n < G4) {
        g_benc[n] = ebih[n] + ebhh[n];
        g_bdec[n] = dbih[n] + dbhh[n];
    }
}

// ======================= prep: x transpose [b][t][i] -> [t][b][i] fp16 =======================
__global__ void prep_x(const float* __restrict__ x) {
    size_t n = (size_t)blockIdx.x * blockDim.x + threadIdx.x;
    if (n < (size_t)TS * NBAT * INP) {
        int i = (int)(n & 31);
        int b = (int)((n >> 5) & 511);
        int t = (int)(n >> 14);
        g_xT[n] = __float2half(x[((size_t)b << 14) + (size_t)t * INP + i]);
    }
}

// ======================= encoder: 512 recurrent steps, weight-stationary =======================
__global__ void __launch_bounds__(256, 1) enc_kernel(const float* __restrict__ x_unused) {
    __shared__ __half h_sm[NB * HSTR];
    __shared__ __half x_sm[2][NB * XSTR];

    const int tid  = threadIdx.x;
    const int w    = tid >> 5;
    const int lane = tid & 31;
    const int g    = lane >> 2;
    const int q    = lane & 3;
    const int bbase = blockIdx.x * NB;

    // zero h state
    for (int j = tid; j < NB * HSTR; j += 256) h_sm[j] = __float2half(0.0f);

    // ---- load stationary A fragments: Whh (8 k-tiles) + Wih (2 k-tiles) ----
    uint32_t aW[4][8][4];
    uint32_t aX[4][2][4];
#pragma unroll
    for (int G = 0; G < 4; G++) {
        const int R = G * 128 + w * 16;
#pragma unroll
        for (int kt = 0; kt < 8; kt++) {
            const int col = kt * 16 + 2 * q;
            aW[G][kt][0] = *(const uint32_t*)&g_WencHH[(R + g) * 128 + col];
            aW[G][kt][1] = *(const uint32_t*)&g_WencHH[(R + g + 8) * 128 + col];
            aW[G][kt][2] = *(const uint32_t*)&g_WencHH[(R + g) * 128 + col + 8];
            aW[G][kt][3] = *(const uint32_t*)&g_WencHH[(R + g + 8) * 128 + col + 8];
        }
#pragma unroll
        for (int kt = 0; kt < 2; kt++) {
            const int col = kt * 16 + 2 * q;
            aX[G][kt][0] = *(const uint32_t*)&g_WencIH[(R + g) * 32 + col];
            aX[G][kt][1] = *(const uint32_t*)&g_WencIH[(R + g + 8) * 32 + col];
            aX[G][kt][2] = *(const uint32_t*)&g_WencIH[(R + g) * 32 + col + 8];
            aX[G][kt][3] = *(const uint32_t*)&g_WencIH[(R + g + 8) * 32 + col + 8];
        }
    }

    // per-thread bias (row-dependent only)
    float bias[4][2];
#pragma unroll
    for (int G = 0; G < 4; G++) {
        bias[G][0] = g_benc[G * 128 + w * 16 + g];
        bias[G][1] = g_benc[G * 128 + w * 16 + g + 8];
    }

    float c[4] = {0.f, 0.f, 0.f, 0.f};

    // preload x for t=0
    if (tid < 128) {
        uint32_t v = *(const uint32_t*)&g_xT[(size_t)bbase * INP + tid * 2];
        int b = tid >> 4, u = tid & 15;
        *(uint32_t*)&x_sm[0][b * XSTR + 2 * u] = v;
    }
    __syncthreads();

    const int r0 = w * 16 + g;
    const int r1 = w * 16 + g + 8;

    for (int t = 0; t < TS; t++) {
        const int cur = t & 1;

        // prefetch next x into regs (latency hidden behind B-frag reads)
        uint32_t xreg = 0;
        if (t < TS - 1 && tid < 128)
            xreg = *(const uint32_t*)&g_xT[(size_t)(t + 1) * (NBAT * INP) + (size_t)bbase * INP + tid * 2];

        // build B fragments from h_sm / x_sm (conflict-free via padding)
        uint32_t bf[8][2], bx[2][2];
#pragma unroll
        for (int kt = 0; kt < 8; kt++) {
            bf[kt][0] = *(const uint32_t*)&h_sm[g * HSTR + kt * 16 + 2 * q];
            bf[kt][1] = *(const uint32_t*)&h_sm[g * HSTR + kt * 16 + 2 * q + 8];
        }
#pragma unroll
        for (int kt = 0; kt < 2; kt++) {
            bx[kt][0] = *(const uint32_t*)&x_sm[cur][g * XSTR + kt * 16 + 2 * q];
            bx[kt][1] = *(const uint32_t*)&x_sm[cur][g * XSTR + kt * 16 + 2 * q + 8];
        }
        __syncthreads();   // reads done; safe to overwrite

        if (t < TS - 1 && tid < 128) {
            int b = tid >> 4, u = tid & 15;
            *(uint32_t*)&x_sm[cur ^ 1][b * XSTR + 2 * u] = xreg;
        }

        // gates = bias + W@h^T (+ Wih@x^T)
        float acc[4][4];
#pragma unroll
        for (int G = 0; G < 4; G++) {
            acc[G][0] = bias[G][0]; acc[G][1] = bias[G][0];
            acc[G][2] = bias[G][1]; acc[G][3] = bias[G][1];
        }
#pragma unroll
        for (int G = 0; G < 4; G++) {
#pragma unroll
            for (int kt = 0; kt < 8; kt++) MMA16816(acc[G], aW[G][kt], bf[kt]);
#pragma unroll
            for (int kt = 0; kt < 2; kt++) MMA16816(acc[G], aX[G][kt], bx[kt]);
        }

        // cell update (thread-local: i,f,g,o aligned across fragments)
#pragma unroll
        for (int j = 0; j < 4; j++) {
            float iv = sigf(acc[0][j]);
            float fv = sigf(acc[1][j]);
            float gv = tanhf_fast(acc[2][j]);
            float ov = sigf(acc[3][j]);
            c[j] = fmaf(fv, c[j], iv * gv);
            float hv = ov * tanhf_fast(c[j]);
            int r = (j < 2) ? r0 : r1;
            int n = 2 * q + (j & 1);
            h_sm[n * HSTR + r] = __float2half(hv);
        }
        __syncthreads();
    }

    // write enc_c (fp32, from regs) and enc_h (fp16, from h_sm)
#pragma unroll
    for (int j = 0; j < 4; j++) {
        int r = (j < 2) ? r0 : r1;
        int n = 2 * q + (j & 1);
        g_encc[(bbase + n) * HID + r] = c[j];
    }
    for (int j = tid; j < NB * HID; j += 256) {
        int b = j >> 7, r = j & 127;
        g_ench[(bbase + b) * HID + r] = h_sm[b * HSTR + r];
    }
}

// ======================= decoder step 0: h1 = cell(0, enc_h, enc_c) with dec_Whh =======================
__global__ void dec_step0(const float* __restrict__ dWhh) {
    __shared__ float hs[HID];
    const int b = blockIdx.x;
    const int h = threadIdx.x;   // 128 threads

    hs[h] = __half2float(g_ench[b * HID + h]);
    __syncthreads();

    float a0 = 0.f, a1 = 0.f, a2 = 0.f, a3 = 0.f;
#pragma unroll 4
    for (int k = 0; k < HID; k++) {
        float hv = hs[k];
        a0 = fmaf(dWhh[(h)*HID + k], hv, a0);
        a1 = fmaf(dWhh[(128 + h) * HID + k], hv, a1);
        a2 = fmaf(dWhh[(256 + h) * HID + k], hv, a2);
        a3 = fmaf(dWhh[(384 + h) * HID + k], hv, a3);
    }
    a0 += g_bdec[h]; a1 += g_bdec[128 + h]; a2 += g_bdec[256 + h]; a3 += g_bdec[384 + h];

    float iv = sigf(a0), fv = sigf(a1), gv = tanhf_fast(a2), ov = sigf(a3);
    float cn = fmaf(fv, g_encc[b * HID + h], iv * gv);
    float h1 = ov * tanhf_fast(cn);
    g_dech[(size_t)b * HID + h] = __float2half(h1);   // t=0 slot
}

// ======================= decoder main: steps 1..511, combined weights, constant c =======================
__global__ void __launch_bounds__(256, 1) dec_kernel() {
    __shared__ __half h_sm[NB * HSTR];

    const int tid  = threadIdx.x;
    const int w    = tid >> 5;
    const int lane = tid & 31;
    const int g    = lane >> 2;
    const int q    = lane & 3;
    const int bbase = blockIdx.x * NB;

    // stationary A fragments: Wcomb
    uint32_t aW[4][8][4];
#pragma unroll
    for (int G = 0; G < 4; G++) {
        const int R = G * 128 + w * 16;
#pragma unroll
        for (int kt = 0; kt < 8; kt++) {
            const int col = kt * 16 + 2 * q;
            aW[G][kt][0] = *(const uint32_t*)&g_Wcomb[(R + g) * 128 + col];
            aW[G][kt][1] = *(const uint32_t*)&g_Wcomb[(R + g + 8) * 128 + col];
            aW[G][kt][2] = *(const uint32_t*)&g_Wcomb[(R + g) * 128 + col + 8];
            aW[G][kt][3] = *(const uint32_t*)&g_Wcomb[(R + g + 8) * 128 + col + 8];
        }
    }
    float bias[4][2];
#pragma unroll
    for (int G = 0; G < 4; G++) {
        bias[G][0] = g_bdec[G * 128 + w * 16 + g];
        bias[G][1] = g_bdec[G * 128 + w * 16 + g + 8];
    }

    const int r0 = w * 16 + g;
    const int r1 = w * 16 + g + 8;

    // constant cell state = enc_c
    float c[4];
#pragma unroll
    for (int j = 0; j < 4; j++) {
        int r = (j < 2) ? r0 : r1;
        int n = 2 * q + (j & 1);
        c[j] = g_encc[(bbase + n) * HID + r];
    }

    // h state init = h1 (= dec_h[0])
    for (int j = tid; j < (NB * HID) / 2; j += 256) {
        uint32_t v = ((const uint32_t*)&g_dech[(size_t)bbase * HID])[j];
        int b = j >> 6, kp = j & 63;
        *(uint32_t*)&h_sm[b * HSTR + 2 * kp] = v;
    }
    __syncthreads();

    for (int t = 1; t < TS; t++) {
        uint32_t bf[8][2];
#pragma unroll
        for (int kt = 0; kt < 8; kt++) {
            bf[kt][0] = *(const uint32_t*)&h_sm[g * HSTR + kt * 16 + 2 * q];
            bf[kt][1] = *(const uint32_t*)&h_sm[g * HSTR + kt * 16 + 2 * q + 8];
        }
        __syncthreads();

        float acc[4][4];
#pragma unroll
        for (int G = 0; G < 4; G++) {
            acc[G][0] = bias[G][0]; acc[G][1] = bias[G][0];
            acc[G][2] = bias[G][1]; acc[G][3] = bias[G][1];
        }
#pragma unroll
        for (int G = 0; G < 4; G++) {
#pragma unroll
            for (int kt = 0; kt < 8; kt++) MMA16816(acc[G], aW[G][kt], bf[kt]);
        }

#pragma unroll
        for (int j = 0; j < 4; j++) {
            float iv = sigf(acc[0][j]);
            float fv = sigf(acc[1][j]);
            float gv = tanhf_fast(acc[2][j]);
            float ov = sigf(acc[3][j]);
            float cn = fmaf(fv, c[j], iv * gv);   // c constant (reset to enc_c every step)
            float hv = ov * tanhf_fast(cn);
            int r = (j < 2) ? r0 : r1;
            int n = 2 * q + (j & 1);
            h_sm[n * HSTR + r] = __float2half(hv);
        }
        __syncthreads();

        // stream h_t to global (coalesced)
        for (int j = tid; j < (NB * HID) / 2; j += 256) {
            int b = j >> 6, kp = j & 63;
            uint32_t v = *(const uint32_t*)&h_sm[b * HSTR + 2 * kp];
            ((uint32_t*)&g_dech[(size_t)t * (NBAT * HID) + (size_t)bbase * HID])[j] = v;
        }
    }
}

// ======================= FC head: out[b][t][i] = dec_h[t][b][:] @ fcW^T + fc_b =======================
__global__ void __launch_bounds__(256) fc_kernel(const float* __restrict__ fc_b,
                                                 float* __restrict__ out) {
    const int tid  = threadIdx.x;
    const int w    = tid >> 5;
    const int lane = tid & 31;
    const int g    = lane >> 2;
    const int q    = lane & 3;

    // B fragments (fcW) resident: 4 n-tiles x 8 k-tiles x 2 regs
    uint32_t bfc[4][8][2];
#pragma unroll
    for (int nt = 0; nt < 4; nt++)
#pragma unroll
        for (int kt = 0; kt < 8; kt++) {
            bfc[nt][kt][0] = *(const uint32_t*)&g_fcW[(nt * 8 + g) * HID + kt * 16 + 2 * q];
            bfc[nt][kt][1] = *(const uint32_t*)&g_fcW[(nt * 8 + g) * HID + kt * 16 + 2 * q + 8];
        }
    float fb0[4], fb1[4];
#pragma unroll
    for (int nt = 0; nt < 4; nt++) {
        fb0[nt] = fc_b[nt * 8 + 2 * q];
        fb1[nt] = fc_b[nt * 8 + 2 * q + 1];
    }

    const int warp_global = blockIdx.x * 8 + w;         // 4096 warps
    const int total_mtiles = (TS * NBAT) / 16;          // 16384

    for (int mt = warp_global; mt < total_mtiles; mt += 4096) {
        const int row0 = mt * 16 + g;
        const int row1 = row0 + 8;

        float acc[4][4];
#pragma unroll
        for (int nt = 0; nt < 4; nt++) {
            acc[nt][0] = fb0[nt]; acc[nt][1] = fb1[nt];
            acc[nt][2] = fb0[nt]; acc[nt][3] = fb1[nt];
        }
#pragma unroll
        for (int kt = 0; kt < 8; kt++) {
            uint32_t a[4];
            const int col = kt * 16 + 2 * q;
            a[0] = *(const uint32_t*)&g_dech[(size_t)row0 * HID + col];
            a[1] = *(const uint32_t*)&g_dech[(size_t)row1 * HID + col];
            a[2] = *(const uint32_t*)&g_dech[(size_t)row0 * HID + col + 8];
            a[3] = *(const uint32_t*)&g_dech[(size_t)row1 * HID + col + 8];
#pragma unroll
            for (int nt = 0; nt < 4; nt++) MMA16816(acc[nt], a, bfc[nt][kt]);
        }

        // scatter to out[b][t][i]: rows r = t*512 + b
        {
            const int b0 = row0 & 511, t0 = row0 >> 9;
            const int b1 = row1 & 511, t1 = row1 >> 9;
            float* p0 = out + (size_t)b0 * (TS * INP) + t0 * INP + 2 * q;
            float* p1 = out + (size_t)b1 * (TS * INP) + t1 * INP + 2 * q;
#pragma unroll
            for (int nt = 0; nt < 4; nt++) {
                *(float2*)(p0 + nt * 8) = make_float2(acc[nt][0], acc[nt][1]);
                *(float2*)(p1 + nt * 8) = make_float2(acc[nt][2], acc[nt][3]);
            }
        }
    }
}

// ======================= launch =======================
extern "C" void kernel_launch(void* const* d_in, const int* in_sizes, int n_in,
                              void* d_out, int out_size) {
    const float* x     = (const float*)d_in[0];
    const float* eWih  = (const float*)d_in[1];
    const float* eWhh  = (const float*)d_in[2];
    const float* ebih  = (const float*)d_in[3];
    const float* ebhh  = (const float*)d_in[4];
    const float* dWih  = (const float*)d_in[5];
    const float* dWhh  = (const float*)d_in[6];
    const float* dbih  = (const float*)d_in[7];
    const float* dbhh  = (const float*)d_in[8];
    const float* fcW   = (const float*)d_in[9];
    const float* fcb   = (const float*)d_in[10];
    float* out = (float*)d_out;

    prep_weights<<<(G4 * HID + 255) / 256, 256>>>(eWih, eWhh, ebih, ebhh, dWih, dWhh, dbih, dbhh, fcW);
    prep_x<<<((size_t)TS * NBAT * INP + 255) / 256, 256>>>(x);
    enc_kernel<<<NBAT / NB, 256>>>(x);
    dec_step0<<<NBAT, 128>>>(dWhh);
    dec_kernel<<<NBAT / NB, 256>>>();
    fc_kernel<<<512, 256>>>(fcb, out);
}

// round 3
// speedup vs baseline: 1.4733x; 1.4733x over previous
#include <cuda_runtime.h>
#include <cuda_fp16.h>
#include <cstdint>

#define TS    512
#define NBAT  512
#define HID   128
#define INP   32
#define G4    512
#define NB    8
#define HSTR  136   // padded h_sm row stride (halfs) -> conflict-free B-frag reads
#define XSTR  40    // padded x_sm row stride (halfs)

// ---------------- device-global scratch (no runtime allocation allowed) ----------------
__device__ __half g_WencHH[G4 * HID];          // enc_Whh fp16
__device__ __half g_WencIH[G4 * INP];          // enc_Wih fp16
__device__ __half g_WdecHH[G4 * HID];          // dec_Whh fp16 (decoder step 0)
__device__ __half g_Wcomb [G4 * HID];          // dec_Wih + dec_Whh fp16 (steps >=1, inp==h)
__device__ float  g_benc[G4];                  // enc_bih + enc_bhh
__device__ float  g_bdec[G4];                  // dec_bih + dec_bhh
__device__ __half g_fcW[INP * HID];            // fc_W fp16
__device__ __half g_xT[(size_t)TS * NBAT * INP];         // [t][b][i]  16MB
__device__ __half g_ench[NBAT * HID];          // encoder final h (fp16)
__device__ float  g_encc[NBAT * HID];          // encoder final c (fp32)
__device__ __half g_dech[(size_t)TS * NBAT * HID];       // [t][b][h]  64MB

// ---------------- activations: single-MUFU tanh.approx ----------------
__device__ __forceinline__ float tanh_apx(float x) {
    float r; asm("tanh.approx.f32 %0, %1;" : "=f"(r) : "f"(x)); return r;
}
__device__ __forceinline__ float sig_apx(float x) {
    return fmaf(0.5f, tanh_apx(0.5f * x), 0.5f);
}

// ---------------- mma.m16n8k16 row.col f32.f16.f16.f32 ----------------
#define MMA16816(acc, a, b)                                                        \
    asm("mma.sync.aligned.m16n8k16.row.col.f32.f16.f16.f32 "                       \
        "{%0,%1,%2,%3}, {%4,%5,%6,%7}, {%8,%9}, {%0,%1,%2,%3};"                    \
        : "+f"(acc[0]), "+f"(acc[1]), "+f"(acc[2]), "+f"(acc[3])                   \
        : "r"(a[0]), "r"(a[1]), "r"(a[2]), "r"(a[3]), "r"(b[0]), "r"(b[1]))

// ======================= prep: weight conversion =======================
__global__ void prep_weights(const float* __restrict__ eWih, const float* __restrict__ eWhh,
                             const float* __restrict__ ebih, const float* __restrict__ ebhh,
                             const float* __restrict__ dWih, const float* __restrict__ dWhh,
                             const float* __restrict__ dbih, const float* __restrict__ dbhh,
                             const float* __restrict__ fcW) {
    int n = blockIdx.x * blockDim.x + threadIdx.x;
    if (n < G4 * HID) {
        g_WencHH[n] = __float2half(eWhh[n]);
        g_WdecHH[n] = __float2half(dWhh[n]);
        g_Wcomb[n]  = __float2half(dWih[n] + dWhh[n]);
    }
    if (n < G4 * INP) g_WencIH[n] = __float2half(eWih[n]);
    if (n < INP * HID) g_fcW[n] = __float2half(fcW[n]);
    if (n < G4) {
        g_benc[n] = ebih[n] + ebhh[n];
        g_bdec[n] = dbih[n] + dbhh[n];
    }
}

// ======================= prep: x transpose [b][t][i] -> [t][b][i] fp16 =======================
__global__ void prep_x(const float* __restrict__ x) {
    size_t n = (size_t)blockIdx.x * blockDim.x + threadIdx.x;
    if (n < (size_t)TS * NBAT * INP) {
        int i = (int)(n & 31);
        int b = (int)((n >> 5) & 511);
        int t = (int)(n >> 14);
        g_xT[n] = __float2half(x[((size_t)b << 14) + (size_t)t * INP + i]);
    }
}

// ======================= encoder: 512 recurrent steps, weight-stationary, 1 bar/step =======================
__global__ void __launch_bounds__(256, 1) enc_kernel() {
    __shared__ __half h_sm[2][NB * HSTR];
    __shared__ __half x_sm[2][NB * XSTR];

    const int tid  = threadIdx.x;
    const int w    = tid >> 5;
    const int lane = tid & 31;
    const int g    = lane >> 2;
    const int q    = lane & 3;
    const int bbase = blockIdx.x * NB;

    // zero h state (buffer 0 is read at t=0)
    for (int j = tid; j < NB * HSTR; j += 256) h_sm[0][j] = __float2half(0.0f);

    // ---- stationary A fragments: Whh (8 k-tiles) + Wih (2 k-tiles) ----
    uint32_t aW[4][8][4];
    uint32_t aX[4][2][4];
#pragma unroll
    for (int G = 0; G < 4; G++) {
        const int R = G * 128 + w * 16;
#pragma unroll
        for (int kt = 0; kt < 8; kt++) {
            const int col = kt * 16 + 2 * q;
            aW[G][kt][0] = *(const uint32_t*)&g_WencHH[(R + g) * 128 + col];
            aW[G][kt][1] = *(const uint32_t*)&g_WencHH[(R + g + 8) * 128 + col];
            aW[G][kt][2] = *(const uint32_t*)&g_WencHH[(R + g) * 128 + col + 8];
            aW[G][kt][3] = *(const uint32_t*)&g_WencHH[(R + g + 8) * 128 + col + 8];
        }
#pragma unroll
        for (int kt = 0; kt < 2; kt++) {
            const int col = kt * 16 + 2 * q;
            aX[G][kt][0] = *(const uint32_t*)&g_WencIH[(R + g) * 32 + col];
            aX[G][kt][1] = *(const uint32_t*)&g_WencIH[(R + g + 8) * 32 + col];
            aX[G][kt][2] = *(const uint32_t*)&g_WencIH[(R + g) * 32 + col + 8];
            aX[G][kt][3] = *(const uint32_t*)&g_WencIH[(R + g + 8) * 32 + col + 8];
        }
    }

    float bias[4][2];
#pragma unroll
    for (int G = 0; G < 4; G++) {
        bias[G][0] = g_benc[G * 128 + w * 16 + g];
        bias[G][1] = g_benc[G * 128 + w * 16 + g + 8];
    }

    float c[4] = {0.f, 0.f, 0.f, 0.f};

    // preload x for t=0 into x_sm[0]
    if (tid < 128) {
        uint32_t v = *(const uint32_t*)&g_xT[(size_t)bbase * INP + tid * 2];
        int b = tid >> 4, u = tid & 15;
        *(uint32_t*)&x_sm[0][b * XSTR + 2 * u] = v;
    }
    __syncthreads();

    const int r0 = w * 16 + g;
    const int r1 = w * 16 + g + 8;

    for (int t = 0; t < TS; t++) {
        const int cur = t & 1;

        // prefetch next x (off critical path)
        uint32_t xreg = 0;
        if (t < TS - 1 && tid < 128)
            xreg = *(const uint32_t*)&g_xT[(size_t)(t + 1) * (NBAT * INP) + (size_t)bbase * INP + tid * 2];

        // B fragments (conflict-free)
        uint32_t bf[8][2], bx[2][2];
#pragma unroll
        for (int kt = 0; kt < 8; kt++) {
            bf[kt][0] = *(const uint32_t*)&h_sm[cur][g * HSTR + kt * 16 + 2 * q];
            bf[kt][1] = *(const uint32_t*)&h_sm[cur][g * HSTR + kt * 16 + 2 * q + 8];
        }
#pragma unroll
        for (int kt = 0; kt < 2; kt++) {
            bx[kt][0] = *(const uint32_t*)&x_sm[cur][g * XSTR + kt * 16 + 2 * q];
            bx[kt][1] = *(const uint32_t*)&x_sm[cur][g * XSTR + kt * 16 + 2 * q + 8];
        }

        // stage next x into the other buffer (readers of that buffer finished last iter)
        if (t < TS - 1 && tid < 128) {
            int b = tid >> 4, u = tid & 15;
            *(uint32_t*)&x_sm[cur ^ 1][b * XSTR + 2 * u] = xreg;
        }

        float acc[4][4];
#pragma unroll
        for (int G = 0; G < 4; G++) {
            acc[G][0] = bias[G][0]; acc[G][1] = bias[G][0];
            acc[G][2] = bias[G][1]; acc[G][3] = bias[G][1];
        }
#pragma unroll
        for (int G = 0; G < 4; G++) {
#pragma unroll
            for (int kt = 0; kt < 8; kt++) MMA16816(acc[G], aW[G][kt], bf[kt]);
#pragma unroll
            for (int kt = 0; kt < 2; kt++) MMA16816(acc[G], aX[G][kt], bx[kt]);
        }

#pragma unroll
        for (int j = 0; j < 4; j++) {
            float iv = sig_apx(acc[0][j]);
            float fv = sig_apx(acc[1][j]);
            float gv = tanh_apx(acc[2][j]);
            float ov = sig_apx(acc[3][j]);
            c[j] = fmaf(fv, c[j], iv * gv);
            float hv = ov * tanh_apx(c[j]);
            int r = (j < 2) ? r0 : r1;
            int n = 2 * q + (j & 1);
            h_sm[cur ^ 1][n * HSTR + r] = __float2half(hv);
        }
        __syncthreads();   // single barrier per step
    }

    // final h is in h_sm[0] (t=511 wrote buffer (1^1)=0)
#pragma unroll
    for (int j = 0; j < 4; j++) {
        int r = (j < 2) ? r0 : r1;
        int n = 2 * q + (j & 1);
        g_encc[(bbase + n) * HID + r] = c[j];
    }
    for (int j = tid; j < NB * HID; j += 256) {
        int b = j >> 7, r = j & 127;
        g_ench[(bbase + b) * HID + r] = h_sm[0][b * HSTR + r];
    }
}

// ======================= decoder: step 0 (Whh only) + steps 1..511 (Wcomb), merged =======================
__global__ void __launch_bounds__(256, 1) dec_kernel() {
    __shared__ __half h_sm[2][NB * HSTR];

    const int tid  = threadIdx.x;
    const int w    = tid >> 5;
    const int lane = tid & 31;
    const int g    = lane >> 2;
    const int q    = lane & 3;
    const int bbase = blockIdx.x * NB;

    const int r0 = w * 16 + g;
    const int r1 = w * 16 + g + 8;

    uint32_t aW[4][8][4];
    // load A fragments from a given weight matrix
    auto load_aW = [&](const __half* Wsrc) {
#pragma unroll
        for (int G = 0; G < 4; G++) {
            const int R = G * 128 + w * 16;
#pragma unroll
            for (int kt = 0; kt < 8; kt++) {
                const int col = kt * 16 + 2 * q;
                aW[G][kt][0] = *(const uint32_t*)&Wsrc[(R + g) * 128 + col];
                aW[G][kt][1] = *(const uint32_t*)&Wsrc[(R + g + 8) * 128 + col];
                aW[G][kt][2] = *(const uint32_t*)&Wsrc[(R + g) * 128 + col + 8];
                aW[G][kt][3] = *(const uint32_t*)&Wsrc[(R + g + 8) * 128 + col + 8];
            }
        }
    };

    float bias[4][2];
#pragma unroll
    for (int G = 0; G < 4; G++) {
        bias[G][0] = g_bdec[G * 128 + w * 16 + g];
        bias[G][1] = g_bdec[G * 128 + w * 16 + g + 8];
    }

    // constant cell state = enc_c (decoder resets c every step)
    float c[4];
#pragma unroll
    for (int j = 0; j < 4; j++) {
        int r = (j < 2) ? r0 : r1;
        int n = 2 * q + (j & 1);
        c[j] = g_encc[(bbase + n) * HID + r];
    }

    // init h_sm[0] = enc_h
    for (int j = tid; j < (NB * HID) / 2; j += 256) {
        uint32_t v = ((const uint32_t*)&g_ench[(size_t)bbase * HID])[j];
        int b = j >> 6, kp = j & 63;
        *(uint32_t*)&h_sm[0][b * HSTR + 2 * kp] = v;
    }
    __syncthreads();

    // one recurrent step: read h_sm[t&1], write h_sm[(t&1)^1], stream g_dech[t]
    auto do_step = [&](int t) {
        const int cur = t & 1;
        uint32_t bf[8][2];
#pragma unroll
        for (int kt = 0; kt < 8; kt++) {
            bf[kt][0] = *(const uint32_t*)&h_sm[cur][g * HSTR + kt * 16 + 2 * q];
            bf[kt][1] = *(const uint32_t*)&h_sm[cur][g * HSTR + kt * 16 + 2 * q + 8];
        }

        float acc[4][4];
#pragma unroll
        for (int G = 0; G < 4; G++) {
            acc[G][0] = bias[G][0]; acc[G][1] = bias[G][0];
            acc[G][2] = bias[G][1]; acc[G][3] = bias[G][1];
        }
#pragma unroll
        for (int G = 0; G < 4; G++) {
#pragma unroll
            for (int kt = 0; kt < 8; kt++) MMA16816(acc[G], aW[G][kt], bf[kt]);
        }

#pragma unroll
        for (int j = 0; j < 4; j++) {
            float iv = sig_apx(acc[0][j]);
            float fv = sig_apx(acc[1][j]);
            float gv = tanh_apx(acc[2][j]);
            float ov = sig_apx(acc[3][j]);
            float cn = fmaf(fv, c[j], iv * gv);   // c constant across steps
            float hv = ov * tanh_apx(cn);
            int r = (j < 2) ? r0 : r1;
            int n = 2 * q + (j & 1);
            h_sm[cur ^ 1][n * HSTR + r] = __float2half(hv);
        }
        __syncthreads();   // single barrier per step

        // stream h_{t+1} (= frame t hidden) to global, coalesced
        for (int j2 = tid; j2 < (NB * HID) / 2; j2 += 256) {
            int b = j2 >> 6, kp = j2 & 63;
            uint32_t v = *(const uint32_t*)&h_sm[cur ^ 1][b * HSTR + 2 * kp];
            ((uint32_t*)&g_dech[(size_t)t * (NBAT * HID) + (size_t)bbase * HID])[j2] = v;
        }
    };

    // step 0: input is zero -> gates = dec_Whh @ enc_h
    load_aW(g_WdecHH);
    do_step(0);

    // steps 1..511: inp == h -> combined weights; reuse the same A registers
    load_aW(g_Wcomb);
    for (int t = 1; t < TS; t++) do_step(t);
}

// ======================= FC head: out[b][t][i] = dec_h[t][b][:] @ fcW^T + fc_b =======================
__global__ void __launch_bounds__(256) fc_kernel(const float* __restrict__ fc_b,
                                                 float* __restrict__ out) {
    const int tid  = threadIdx.x;
    const int w    = tid >> 5;
    const int lane = tid & 31;
    const int g    = lane >> 2;
    const int q    = lane & 3;

    uint32_t bfc[4][8][2];
#pragma unroll
    for (int nt = 0; nt < 4; nt++)
#pragma unroll
        for (int kt = 0; kt < 8; kt++) {
            bfc[nt][kt][0] = *(const uint32_t*)&g_fcW[(nt * 8 + g) * HID + kt * 16 + 2 * q];
            bfc[nt][kt][1] = *(const uint32_t*)&g_fcW[(nt * 8 + g) * HID + kt * 16 + 2 * q + 8];
        }
    float fb0[4], fb1[4];
#pragma unroll
    for (int nt = 0; nt < 4; nt++) {
        fb0[nt] = fc_b[nt * 8 + 2 * q];
        fb1[nt] = fc_b[nt * 8 + 2 * q + 1];
    }

    const int warp_global = blockIdx.x * 8 + w;
    const int total_mtiles = (TS * NBAT) / 16;

    for (int mt = warp_global; mt < total_mtiles; mt += 4096) {
        const int row0 = mt * 16 + g;
        const int row1 = row0 + 8;

        float acc[4][4];
#pragma unroll
        for (int nt = 0; nt < 4; nt++) {
            acc[nt][0] = fb0[nt]; acc[nt][1] = fb1[nt];
            acc[nt][2] = fb0[nt]; acc[nt][3] = fb1[nt];
        }
#pragma unroll
        for (int kt = 0; kt < 8; kt++) {
            uint32_t a[4];
            const int col = kt * 16 + 2 * q;
            a[0] = *(const uint32_t*)&g_dech[(size_t)row0 * HID + col];
            a[1] = *(const uint32_t*)&g_dech[(size_t)row1 * HID + col];
            a[2] = *(const uint32_t*)&g_dech[(size_t)row0 * HID + col + 8];
            a[3] = *(const uint32_t*)&g_dech[(size_t)row1 * HID + col + 8];
#pragma unroll
            for (int nt = 0; nt < 4; nt++) MMA16816(acc[nt], a, bfc[nt][kt]);
        }

        {
            const int b0 = row0 & 511, t0 = row0 >> 9;
            const int b1 = row1 & 511, t1 = row1 >> 9;
            float* p0 = out + (size_t)b0 * (TS * INP) + t0 * INP + 2 * q;
            float* p1 = out + (size_t)b1 * (TS * INP) + t1 * INP + 2 * q;
#pragma unroll
            for (int nt = 0; nt < 4; nt++) {
                *(float2*)(p0 + nt * 8) = make_float2(acc[nt][0], acc[nt][1]);
                *(float2*)(p1 + nt * 8) = make_float2(acc[nt][2], acc[nt][3]);
            }
        }
    }
}

// ======================= launch =======================
extern "C" void kernel_launch(void* const* d_in, const int* in_sizes, int n_in,
                              void* d_out, int out_size) {
    const float* x     = (const float*)d_in[0];
    const float* eWih  = (const float*)d_in[1];
    const float* eWhh  = (const float*)d_in[2];
    const float* ebih  = (const float*)d_in[3];
    const float* ebhh  = (const float*)d_in[4];
    const float* dWih  = (const float*)d_in[5];
    const float* dWhh  = (const float*)d_in[6];
    const float* dbih  = (const float*)d_in[7];
    const float* dbhh  = (const float*)d_in[8];
    const float* fcW   = (const float*)d_in[9];
    const float* fcb   = (const float*)d_in[10];
    float* out = (float*)d_out;

    prep_weights<<<(G4 * HID + 255) / 256, 256>>>(eWih, eWhh, ebih, ebhh, dWih, dWhh, dbih, dbhh, fcW);
    prep_x<<<((size_t)TS * NBAT * INP + 255) / 256, 256>>>(x);
    enc_kernel<<<NBAT / NB, 256>>>();
    dec_kernel<<<NBAT / NB, 256>>>();
    fc_kernel<<<512, 256>>>(fcb, out);
}